// round 15
// baseline (speedup 1.0000x reference)
#include <cuda_runtime.h>
#include <cuda_bf16.h>

#define Cc    9
#define OUTc  16
#define NBc   16
#define Vc    20000
#define Bc    2

typedef unsigned long long u64;

__device__ __forceinline__ u64 pk2(float a, float b) {
    u64 r; asm("mov.b64 %0, {%1, %2};" : "=l"(r) : "f"(a), "f"(b)); return r;
}
__device__ __forceinline__ void upk2(u64 v, float& a, float& b) {
    asm("mov.b64 {%0, %1}, %2;" : "=f"(a), "=f"(b) : "l"(v));
}
__device__ __forceinline__ u64 ffma2(u64 a, u64 b, u64 c) {
    u64 d; asm("fma.rn.f32x2 %0, %1, %2, %3;" : "=l"(d) : "l"(a), "l"(b), "l"(c)); return d;
}
__device__ __forceinline__ void cpa16(unsigned saddr, const void* gaddr) {
    asm volatile("cp.async.ca.shared.global [%0], [%1], 16;"
                 :: "r"(saddr), "l"(gaddr) : "memory");
}

// padded x: 3 float4 per row (48 B)
__device__ __align__(16) float4 xpad[Bc * Vc * 3];

__global__ __launch_bounds__(256)
void pad_kernel(const float* __restrict__ x)
{
    int r = blockIdx.x * blockDim.x + threadIdx.x;
    if (r >= Bc * Vc) return;
    const float* src = x + (size_t)r * Cc;
    float4* dst = xpad + (size_t)r * 3;
    dst[0] = make_float4(__ldg(&src[0]), __ldg(&src[1]), __ldg(&src[2]), __ldg(&src[3]));
    dst[1] = make_float4(__ldg(&src[4]), __ldg(&src[5]), __ldg(&src[6]), __ldg(&src[7]));
    dst[2] = make_float4(__ldg(&src[8]), 0.0f, 0.0f, 0.0f);
}

#define VSTRIDE 49   // float4 per vertex in stage (16 rows * 3 + 1 pad; 784B = 16 mod 128)

__global__ __launch_bounds__(128, 5)
void nlayer_kernel(const float* __restrict__ W,
                   const int*   __restrict__ adj,
                   float*       __restrict__ out)
{
    // W[c][k][o] + 16-float zero pad (absorbs dead-slot k=9, c=8 read)
    __shared__ __align__(16) float  Wsh[Cc * Cc * OUTc + 16];
    __shared__ __align__(16) float4 stage[32 * VSTRIDE];   // 32 vertices/block

    for (int i = threadIdx.x; i < Cc * Cc * OUTc + 16; i += blockDim.x)
        Wsh[i] = (i < Cc * Cc * OUTc) ? W[i] : 0.0f;

    int gid   = blockIdx.x * blockDim.x + threadIdx.x;   // 160000 total, exact
    int group = gid >> 2;          // vertex over B*V
    int l     = gid & 3;
    int p     = l & 1;             // k-parity: k = 2j + p (p=1: j<4 live, j=4 dead)
    int q     = l >> 1;            // neighbor half AND o-half
    int vloc  = (threadIdx.x >> 2);// vertex slot within block (0..31)

    int b = (group >= Vc) ? 1 : 0;
    int v = group - b * Vc;
    const float4* tb = xpad + (size_t)(b * Vc) * 3;

    // adjacency for this lane's q-half (both p lanes load the same -> merged)
    const int4* adj4 = reinterpret_cast<const int4*>(adj + (size_t)v * NBc);
    int4 a0 = __ldg(&adj4[2 * q + 0]);
    int4 a1 = __ldg(&adj4[2 * q + 1]);
    int av[8] = {a0.x, a0.y, a0.z, a0.w, a1.x, a1.y, a1.z, a1.w};

    int deg = 0;
    unsigned vmask = 0;
    int ridx[8];
    #pragma unroll
    for (int n = 0; n < 8; n++) {
        int val = (av[n] != 0);
        deg += val;
        vmask |= (unsigned)val << n;
        ridx[n] = val ? (av[n] - 1) : 0;
    }

    // center row (4 lanes same addr -> merged)
    float4 c0 = __ldg(&tb[(size_t)v * 3 + 0]);
    float4 c1 = __ldg(&tb[(size_t)v * 3 + 1]);
    float4 c2 = __ldg(&tb[(size_t)v * 3 + 2]);
    float xv[Cc] = {c0.x, c0.y, c0.z, c0.w, c1.x, c1.y, c1.z, c1.w, c2.x};

    // ---- stage: this lane stages rows [q*8 + p*4, +4): 12 cp.async, no dup ----
    float4* vbase = stage + vloc * VSTRIDE;
    unsigned sb = (unsigned)__cvta_generic_to_shared(vbase);
    #pragma unroll
    for (int n = 0; n < 4; n++) {
        int row = q * 8 + p * 4 + n;
        const float4* g = &tb[(size_t)ridx[p * 4 + n] * 3];
        unsigned d = sb + (unsigned)(row * 3) * 16;
        cpa16(d,      g);
        cpa16(d + 16, g + 1);
        cpa16(d + 32, g + 2);
    }
    asm volatile("cp.async.commit_group;" ::: "memory");
    asm volatile("cp.async.wait_group 0;" ::: "memory");
    __syncthreads();   // publish staged rows + Wsh

    // deg over both q halves (xor2); all 4 lanes agree
    deg += __shfl_xor_sync(0xffffffffu, deg, 2);
    float invdeg = (deg > 0) ? (1.0f / (float)deg) : 0.0f;

    // center features at this lane's k-slots: k = 2j + p
    float xc[5];
    #pragma unroll
    for (int j = 0; j < 5; j++) {
        int k = 2 * j + p;
        xc[j] = (k < Cc) ? xv[k] : 0.0f;
    }

    // s[j][c]: c0..7 packed, c=8 scalar; j indexes k = 2j+p
    u64   s2[5][4];
    float s8c[5];
    #pragma unroll
    for (int j = 0; j < 5; j++) {
        s2[j][0] = 0ULL; s2[j][1] = 0ULL; s2[j][2] = 0ULL; s2[j][3] = 0ULL;
        s8c[j] = 0.0f;
    }

    // process all 8 neighbors of this q-half from shared
    #pragma unroll
    for (int n = 0; n < 8; n++) {
        const float4* nr = vbase + (q * 8 + n) * 3;
        float4 n0 = nr[0];
        float4 n1 = nr[1];
        float4 n2 = nr[2];
        float nb[Cc] = {n0.x, n0.y, n0.z, n0.w, n1.x, n1.y, n1.z, n1.w, n2.x};
        u64 nbp[4] = {pk2(nb[0], nb[1]), pk2(nb[2], nb[3]),
                      pk2(nb[4], nb[5]), pk2(nb[6], nb[7])};

        // exp for this lane's k-slots only
        float e[5];
        e[0] = __expf(xc[0] - nb[p]);
        e[1] = __expf(xc[1] - nb[2 + p]);
        e[2] = __expf(xc[2] - nb[4 + p]);
        e[3] = __expf(xc[3] - nb[6 + p]);
        e[4] = (p == 0) ? __expf(xc[4] - nb[8]) : 0.0f;

        float part = e[0] + e[1] + e[2] + e[3] + e[4];
        part += __shfl_xor_sync(0xffffffffu, part, 1);   // combine k-parities
        float rr = (vmask >> n) & 1u ? __fdividef(1.0f, part) : 0.0f;

        #pragma unroll
        for (int j = 0; j < 5; j++) {
            float qk = e[j] * rr;
            u64 qq = pk2(qk, qk);
            s2[j][0] = ffma2(qq, nbp[0], s2[j][0]);
            s2[j][1] = ffma2(qq, nbp[1], s2[j][1]);
            s2[j][2] = ffma2(qq, nbp[2], s2[j][2]);
            s2[j][3] = ffma2(qq, nbp[3], s2[j][3]);
            s8c[j]   = fmaf(qk, nb[8], s8c[j]);
        }
    }

    // reduce s across the two q halves (xor2); both get full s for their k-slots
    #pragma unroll
    for (int j = 0; j < 5; j++) {
        #pragma unroll
        for (int i = 0; i < 4; i++) {
            u64 o = __shfl_xor_sync(0xffffffffu, s2[j][i], 2);
            float x0f, x1f, y0f, y1f;
            upk2(s2[j][i], x0f, x1f);
            upk2(o,        y0f, y1f);
            s2[j][i] = pk2(x0f + y0f, x1f + y1f);
        }
        s8c[j] += __shfl_xor_sync(0xffffffffu, s8c[j], 2);
    }

    // contraction: lane's k-slots into o-half [8q, 8q+8)
    u64 ac[4] = {0ULL, 0ULL, 0ULL, 0ULL};
    const float* wb = Wsh + p * OUTc + 8 * q;   // k = 2j+p folded: row (c*9 + 2j + p)
    #pragma unroll
    for (int i = 0; i < 4; i++) {               // c-pairs (2i, 2i+1)
        #pragma unroll
        for (int j = 0; j < 5; j++) {
            float sc0, sc1;
            upk2(s2[j][i], sc0, sc1);
            {
                u64 ss = pk2(sc0, sc0);
                const ulonglong2* wr = reinterpret_cast<const ulonglong2*>(
                    wb + ((2 * i) * Cc + 2 * j) * OUTc);
                ulonglong2 wA = wr[0], wB = wr[1];
                ac[0] = ffma2(ss, wA.x, ac[0]);
                ac[1] = ffma2(ss, wA.y, ac[1]);
                ac[2] = ffma2(ss, wB.x, ac[2]);
                ac[3] = ffma2(ss, wB.y, ac[3]);
            }
            {
                u64 ss = pk2(sc1, sc1);
                const ulonglong2* wr = reinterpret_cast<const ulonglong2*>(
                    wb + ((2 * i + 1) * Cc + 2 * j) * OUTc);
                ulonglong2 wA = wr[0], wB = wr[1];
                ac[0] = ffma2(ss, wA.x, ac[0]);
                ac[1] = ffma2(ss, wA.y, ac[1]);
                ac[2] = ffma2(ss, wB.x, ac[2]);
                ac[3] = ffma2(ss, wB.y, ac[3]);
            }
        }
    }
    #pragma unroll
    for (int j = 0; j < 5; j++) {               // c = 8
        u64 ss = pk2(s8c[j], s8c[j]);
        const ulonglong2* wr = reinterpret_cast<const ulonglong2*>(
            wb + (8 * Cc + 2 * j) * OUTc);      // j=4,p=1 -> k=9 row: hits zero pad / x0 row times s=0
        ulonglong2 wA = wr[0], wB = wr[1];
        ac[0] = ffma2(ss, wA.x, ac[0]);
        ac[1] = ffma2(ss, wA.y, ac[1]);
        ac[2] = ffma2(ss, wB.x, ac[2]);
        ac[3] = ffma2(ss, wB.y, ac[3]);
    }

    // combine k-parities (xor1): both p lanes then hold the full o-half [8q,8q+8)
    #pragma unroll
    for (int i = 0; i < 4; i++) {
        u64 o = __shfl_xor_sync(0xffffffffu, ac[i], 1);
        float x0f, x1f, y0f, y1f;
        upk2(ac[i], x0f, x1f);
        upk2(o,     y0f, y1f);
        ac[i] = pk2(x0f + y0f, x1f + y1f);
    }

    // lane (p,q) stores o in [8q + 4p, +4): one float4; warp covers 1KB contiguous
    float r0f, r1f, r2f, r3f;
    upk2(ac[2 * p + 0], r0f, r1f);
    upk2(ac[2 * p + 1], r2f, r3f);
    float4 o;
    o.x = fmaxf(r0f * invdeg, 0.0f);
    o.y = fmaxf(r1f * invdeg, 0.0f);
    o.z = fmaxf(r2f * invdeg, 0.0f);
    o.w = fmaxf(r3f * invdeg, 0.0f);
    *reinterpret_cast<float4*>(out + (size_t)group * OUTc + 8 * q + 4 * p) = o;
}

extern "C" void kernel_launch(void* const* d_in, const int* in_sizes, int n_in,
                              void* d_out, int out_size)
{
    const float* x   = (const float*)d_in[0];   // (2, 20000, 9)
    const float* W   = (const float*)d_in[1];   // (9, 9, 16)
    const int*   adj = (const int*)d_in[2];     // (20000, 16)
    float*       out = (float*)d_out;           // (2, 20000, 16)

    {
        const int total   = Bc * Vc;            // 40000
        const int threads = 256;
        pad_kernel<<<(total + threads - 1) / threads, threads>>>(x);
    }
    {
        const int total   = Bc * Vc * 4;        // 160000 threads
        const int threads = 128;
        nlayer_kernel<<<total / threads, threads>>>(W, adj, out);
    }
}

// round 16
// speedup vs baseline: 1.2684x; 1.2684x over previous
#include <cuda_runtime.h>
#include <cuda_bf16.h>

#define Cc    9
#define OUTc  16
#define NBc   16
#define Vc    20000
#define Bc    2

typedef unsigned long long u64;

__device__ __forceinline__ u64 pk2(float a, float b) {
    u64 r; asm("mov.b64 %0, {%1, %2};" : "=l"(r) : "f"(a), "f"(b)); return r;
}
__device__ __forceinline__ void upk2(u64 v, float& a, float& b) {
    asm("mov.b64 {%0, %1}, %2;" : "=f"(a), "=f"(b) : "l"(v));
}
__device__ __forceinline__ u64 ffma2(u64 a, u64 b, u64 c) {
    u64 d; asm("fma.rn.f32x2 %0, %1, %2, %3;" : "=l"(d) : "l"(a), "l"(b), "l"(c)); return d;
}

// padded x: 3 float4 per row (48 B)
__device__ __align__(16) float4 xpad[Bc * Vc * 3];

__global__ __launch_bounds__(256)
void pad_kernel(const float* __restrict__ x)
{
    int r = blockIdx.x * blockDim.x + threadIdx.x;
    if (r >= Bc * Vc) return;
    const float* src = x + (size_t)r * Cc;
    float4* dst = xpad + (size_t)r * 3;
    dst[0] = make_float4(__ldg(&src[0]), __ldg(&src[1]), __ldg(&src[2]), __ldg(&src[3]));
    dst[1] = make_float4(__ldg(&src[4]), __ldg(&src[5]), __ldg(&src[6]), __ldg(&src[7]));
    dst[2] = make_float4(__ldg(&src[8]), 0.0f, 0.0f, 0.0f);
}

__global__ __launch_bounds__(128, 4)
void nlayer_kernel(const float* __restrict__ W,
                   const int*   __restrict__ adj,
                   float*       __restrict__ out)
{
    __shared__ __align__(16) float Wsh[Cc * Cc * OUTc];   // W[c][k][o]
    for (int i = threadIdx.x; i < Cc * Cc * OUTc; i += blockDim.x)
        Wsh[i] = W[i];

    int gid   = blockIdx.x * blockDim.x + threadIdx.x;    // 80000 total, exact
    int group = gid >> 1;           // vertex over B*V
    int p     = gid & 1;            // channel half: lane0 c0-3 (k0-3), lane1 c4-8 (k4-8)

    int b = (group >= Vc) ? 1 : 0;
    int v = group - b * Vc;
    const float4* tb = xpad + (size_t)(b * Vc) * 3;

    // center: own chunk + c8 (c8 addr identical across the pair -> merged)
    float4 cch = __ldg(&tb[(size_t)v * 3 + p]);
    float  cx8 = __ldg(reinterpret_cast<const float*>(&tb[(size_t)v * 3 + 2]));

    // full adjacency (same addrs across the pair -> merged)
    const int4* adj4 = reinterpret_cast<const int4*>(adj + (size_t)v * NBc);
    int4 A0 = __ldg(&adj4[0]);
    int4 A1 = __ldg(&adj4[1]);
    int4 A2 = __ldg(&adj4[2]);
    int4 A3 = __ldg(&adj4[3]);
    int av[NBc] = {A0.x, A0.y, A0.z, A0.w, A1.x, A1.y, A1.z, A1.w,
                   A2.x, A2.y, A2.z, A2.w, A3.x, A3.y, A3.z, A3.w};

    __syncthreads();

    int deg = 0;
    unsigned vmask = 0;
    #pragma unroll
    for (int n = 0; n < NBc; n++) {
        int val = (av[n] != 0);
        deg += val;
        vmask |= (unsigned)val << n;
    }
    float invdeg = (deg > 0) ? (1.0f / (float)deg) : 0.0f;

    float xc0 = cch.x, xc1 = cch.y, xc2 = cch.z, xc3 = cch.w;

    // s[k][own c's]: 2 packed c-pairs per k; c8 scalar (meaningful on lane1)
    u64   s2k[Cc][2];
    float s8k[Cc];
    #pragma unroll
    for (int k = 0; k < Cc; k++) { s2k[k][0] = 0ULL; s2k[k][1] = 0ULL; s8k[k] = 0.0f; }

    // 2 bursts of 8 neighbors
    #pragma unroll
    for (int g = 0; g < 2; g++) {
        float4 CH[8];
        float  X8[8];
        #pragma unroll
        for (int n = 0; n < 8; n++) {
            int idx  = g * 8 + n;
            int val  = (vmask >> idx) & 1u;
            int ridx = val ? (av[idx] - 1) : 0;
            CH[n] = __ldg(&tb[(size_t)ridx * 3 + p]);     // own 16B chunk
            X8[n] = __ldg(reinterpret_cast<const float*>(&tb[(size_t)ridx * 3 + 2]));
        }

        #pragma unroll
        for (int n = 0; n < 8; n++) {
            int idx = g * 8 + n;
            float4 ch = CH[n];
            float x8n = X8[n];

            // exps for own channels only
            float e0 = __expf(xc0 - ch.x);
            float e1 = __expf(xc1 - ch.y);
            float e2 = __expf(xc2 - ch.z);
            float e3 = __expf(xc3 - ch.w);
            float e4 = (p == 1) ? __expf(cx8 - x8n) : 0.0f;
            float psum = e0 + e1 + e2 + e3 + e4;

            // exchange exps + partial sum with the partner lane
            u64 m0 = pk2(e0, e1);
            u64 m1 = pk2(e2, e3);
            u64 m2 = pk2(e4, psum);
            u64 o0 = __shfl_xor_sync(0xffffffffu, m0, 1);
            u64 o1 = __shfl_xor_sync(0xffffffffu, m1, 1);
            u64 o2 = __shfl_xor_sync(0xffffffffu, m2, 1);
            float oa, ob, oc, od, oe, osum;
            upk2(o0, oa, ob);
            upk2(o1, oc, od);
            upk2(o2, oe, osum);

            float tot = psum + osum;
            float rr  = ((vmask >> idx) & 1u) ? __fdividef(1.0f, tot) : 0.0f;

            // assemble q in k-order
            float qk[Cc];
            qk[0] = p ? oa : e0;
            qk[1] = p ? ob : e1;
            qk[2] = p ? oc : e2;
            qk[3] = p ? od : e3;
            qk[4] = p ? e0 : oa;
            qk[5] = p ? e1 : ob;
            qk[6] = p ? e2 : oc;
            qk[7] = p ? e3 : od;
            qk[8] = p ? e4 : oe;

            u64 cp0 = pk2(ch.x, ch.y);
            u64 cp1 = pk2(ch.z, ch.w);
            #pragma unroll
            for (int k = 0; k < Cc; k++) {
                float qs = qk[k] * rr;
                u64 qq = pk2(qs, qs);
                s2k[k][0] = ffma2(qq, cp0, s2k[k][0]);
                s2k[k][1] = ffma2(qq, cp1, s2k[k][1]);
                s8k[k]    = fmaf(qs, x8n, s8k[k]);   // only consumed on lane1
            }
        }
    }

    // contraction: own c-range x all k -> full out[16] partial
    u64 ac[8];
    #pragma unroll
    for (int i = 0; i < 8; i++) ac[i] = 0ULL;

    const int cbase = 4 * p;
    #pragma unroll
    for (int cp_i = 0; cp_i < 2; cp_i++) {      // own c-pairs
        #pragma unroll
        for (int k = 0; k < Cc; k++) {
            float sA, sB;
            upk2(s2k[k][cp_i], sA, sB);
            {
                u64 ss = pk2(sA, sA);
                const ulonglong2* wr = reinterpret_cast<const ulonglong2*>(
                    Wsh + ((cbase + 2 * cp_i) * Cc + k) * OUTc);
                ulonglong2 wA = wr[0], wB = wr[1], wC = wr[2], wD = wr[3];
                ac[0] = ffma2(ss, wA.x, ac[0]);
                ac[1] = ffma2(ss, wA.y, ac[1]);
                ac[2] = ffma2(ss, wB.x, ac[2]);
                ac[3] = ffma2(ss, wB.y, ac[3]);
                ac[4] = ffma2(ss, wC.x, ac[4]);
                ac[5] = ffma2(ss, wC.y, ac[5]);
                ac[6] = ffma2(ss, wD.x, ac[6]);
                ac[7] = ffma2(ss, wD.y, ac[7]);
            }
            {
                u64 ss = pk2(sB, sB);
                const ulonglong2* wr = reinterpret_cast<const ulonglong2*>(
                    Wsh + ((cbase + 2 * cp_i + 1) * Cc + k) * OUTc);
                ulonglong2 wA = wr[0], wB = wr[1], wC = wr[2], wD = wr[3];
                ac[0] = ffma2(ss, wA.x, ac[0]);
                ac[1] = ffma2(ss, wA.y, ac[1]);
                ac[2] = ffma2(ss, wB.x, ac[2]);
                ac[3] = ffma2(ss, wB.y, ac[3]);
                ac[4] = ffma2(ss, wC.x, ac[4]);
                ac[5] = ffma2(ss, wC.y, ac[5]);
                ac[6] = ffma2(ss, wD.x, ac[6]);
                ac[7] = ffma2(ss, wD.y, ac[7]);
            }
        }
    }
    if (p == 1) {                               // c = 8 (lane1 owns it)
        #pragma unroll
        for (int k = 0; k < Cc; k++) {
            u64 ss = pk2(s8k[k], s8k[k]);
            const ulonglong2* wr = reinterpret_cast<const ulonglong2*>(
                Wsh + (8 * Cc + k) * OUTc);
            ulonglong2 wA = wr[0], wB = wr[1], wC = wr[2], wD = wr[3];
            ac[0] = ffma2(ss, wA.x, ac[0]);
            ac[1] = ffma2(ss, wA.y, ac[1]);
            ac[2] = ffma2(ss, wB.x, ac[2]);
            ac[3] = ffma2(ss, wB.y, ac[3]);
            ac[4] = ffma2(ss, wC.x, ac[4]);
            ac[5] = ffma2(ss, wC.y, ac[5]);
            ac[6] = ffma2(ss, wD.x, ac[6]);
            ac[7] = ffma2(ss, wD.y, ac[7]);
        }
    }

    // combine c-halves across the pair; both lanes then hold full out[16]
    #pragma unroll
    for (int i = 0; i < 8; i++) {
        u64 o = __shfl_xor_sync(0xffffffffu, ac[i], 1);
        float x0f, x1f, y0f, y1f;
        upk2(ac[i], x0f, x1f);
        upk2(o,     y0f, y1f);
        ac[i] = pk2(x0f + y0f, x1f + y1f);
    }

    // lane p stores outputs [8p, 8p+8): two float4, coalesced
    float r0f, r1f, r2f, r3f, r4f, r5f, r6f, r7f;
    upk2(ac[4 * p + 0], r0f, r1f);
    upk2(ac[4 * p + 1], r2f, r3f);
    upk2(ac[4 * p + 2], r4f, r5f);
    upk2(ac[4 * p + 3], r6f, r7f);

    float* op = out + (size_t)group * OUTc + 8 * p;
    float4 o0, o1;
    o0.x = fmaxf(r0f * invdeg, 0.0f);
    o0.y = fmaxf(r1f * invdeg, 0.0f);
    o0.z = fmaxf(r2f * invdeg, 0.0f);
    o0.w = fmaxf(r3f * invdeg, 0.0f);
    o1.x = fmaxf(r4f * invdeg, 0.0f);
    o1.y = fmaxf(r5f * invdeg, 0.0f);
    o1.z = fmaxf(r6f * invdeg, 0.0f);
    o1.w = fmaxf(r7f * invdeg, 0.0f);
    *reinterpret_cast<float4*>(op)     = o0;
    *reinterpret_cast<float4*>(op + 4) = o1;
}

extern "C" void kernel_launch(void* const* d_in, const int* in_sizes, int n_in,
                              void* d_out, int out_size)
{
    const float* x   = (const float*)d_in[0];   // (2, 20000, 9)
    const float* W   = (const float*)d_in[1];   // (9, 9, 16)
    const int*   adj = (const int*)d_in[2];     // (20000, 16)
    float*       out = (float*)d_out;           // (2, 20000, 16)

    {
        const int total   = Bc * Vc;            // 40000
        const int threads = 256;
        pad_kernel<<<(total + threads - 1) / threads, threads>>>(x);
    }
    {
        const int total   = Bc * Vc * 2;        // 80000 threads
        const int threads = 128;
        nlayer_kernel<<<total / threads, threads>>>(W, adj, out);
    }
}

// round 17
// speedup vs baseline: 1.4975x; 1.1806x over previous
#include <cuda_runtime.h>
#include <cuda_fp16.h>

#define Cc    9
#define OUTc  16
#define NBc   16
#define Vc    20000
#define Bc    2

typedef unsigned long long u64;

__device__ __forceinline__ u64 pk2(float a, float b) {
    u64 r; asm("mov.b64 %0, {%1, %2};" : "=l"(r) : "f"(a), "f"(b)); return r;
}
__device__ __forceinline__ void upk2(u64 v, float& a, float& b) {
    asm("mov.b64 {%0, %1}, %2;" : "=f"(a), "=f"(b) : "l"(v));
}
__device__ __forceinline__ u64 ffma2(u64 a, u64 b, u64 c) {
    u64 d; asm("fma.rn.f32x2 %0, %1, %2, %3;" : "=l"(d) : "l"(a), "l"(b), "l"(c)); return d;
}

// compact gather table: 32B per row = [8 x fp16 (c0..7) | fp32 x8 | 12B pad]
// 32B-aligned rows -> every row lives in exactly ONE 128B line.
__device__ __align__(32) float4 xh[Bc * Vc * 2];

__global__ __launch_bounds__(256)
void pad_kernel(const float* __restrict__ x)
{
    int r = blockIdx.x * blockDim.x + threadIdx.x;   // row over B*V
    if (r >= Bc * Vc) return;
    const float* src = x + (size_t)r * Cc;
    __half2 h0 = __floats2half2_rn(__ldg(&src[0]), __ldg(&src[1]));
    __half2 h1 = __floats2half2_rn(__ldg(&src[2]), __ldg(&src[3]));
    __half2 h2 = __floats2half2_rn(__ldg(&src[4]), __ldg(&src[5]));
    __half2 h3 = __floats2half2_rn(__ldg(&src[6]), __ldg(&src[7]));
    uint4 u;
    u.x = *reinterpret_cast<unsigned*>(&h0);
    u.y = *reinterpret_cast<unsigned*>(&h1);
    u.z = *reinterpret_cast<unsigned*>(&h2);
    u.w = *reinterpret_cast<unsigned*>(&h3);
    xh[2 * r]     = *reinterpret_cast<float4*>(&u);
    xh[2 * r + 1] = make_float4(__ldg(&src[8]), 0.0f, 0.0f, 0.0f);
}

__global__ __launch_bounds__(128, 3)
void nlayer_kernel(const float* __restrict__ x,
                   const float* __restrict__ W,
                   const int*   __restrict__ adj,
                   float*       __restrict__ out)
{
    __shared__ __align__(16) float Wsh[Cc * Cc * OUTc];   // W[c][k][o]
    for (int i = threadIdx.x; i < Cc * Cc * OUTc; i += blockDim.x)
        Wsh[i] = W[i];

    int gid   = blockIdx.x * blockDim.x + threadIdx.x;    // 80000 total, exact
    int group = gid >> 1;          // vertex over B*V
    int p     = gid & 1;           // neighbor half AND output half

    int b = (group >= Vc) ? 1 : 0;
    int v = group - b * Vc;
    size_t rowbase = (size_t)(b * Vc);

    // center: fp32 straight from x (merged across lane pair, streaming-friendly)
    const float* cx = x + (rowbase + v) * Cc;
    float xv[Cc];
    #pragma unroll
    for (int c = 0; c < Cc; c++) xv[c] = __ldg(&cx[c]);

    // this lane's 8 neighbors
    const int4* adj4 = reinterpret_cast<const int4*>(adj + (size_t)v * NBc);
    int4 a0 = __ldg(&adj4[2 * p + 0]);
    int4 a1 = __ldg(&adj4[2 * p + 1]);
    int av[8] = {a0.x, a0.y, a0.z, a0.w, a1.x, a1.y, a1.z, a1.w};

    int deg = 0;
    unsigned vmask = 0;
    #pragma unroll
    for (int n = 0; n < 8; n++) {
        int val = (av[n] != 0);
        deg += val;
        vmask |= (unsigned)val << n;
    }

    // full 8-row gather burst: per row 1 LDG.128 + 1 LDG.32, SAME 128B line
    uint4 H[8];
    float X8[8];
    #pragma unroll
    for (int n = 0; n < 8; n++) {
        int ridx = ((vmask >> n) & 1u) ? (av[n] - 1) : 0;
        size_t base = (rowbase + (size_t)ridx) * 2;
        H[n]  = __ldg(reinterpret_cast<const uint4*>(&xh[base]));
        X8[n] = __ldg(reinterpret_cast<const float*>(&xh[base + 1]));
    }

    __syncthreads();   // Wsh ready; gathers above ride over the barrier

    deg += __shfl_xor_sync(0xffffffffu, deg, 1);
    float invdeg = (deg > 0) ? (1.0f / (float)deg) : 0.0f;

    // s[k][c]: c0..7 packed as 4 f32x2 per k, c=8 scalar
    u64   s2[Cc][4];
    float s8c[Cc];
    #pragma unroll
    for (int k = 0; k < Cc; k++) {
        s2[k][0] = 0ULL; s2[k][1] = 0ULL; s2[k][2] = 0ULL; s2[k][3] = 0ULL;
        s8c[k] = 0.0f;
    }

    #pragma unroll
    for (int n = 0; n < 8; n++) {
        float2 f01 = __half22float2(*reinterpret_cast<__half2*>(&H[n].x));
        float2 f23 = __half22float2(*reinterpret_cast<__half2*>(&H[n].y));
        float2 f45 = __half22float2(*reinterpret_cast<__half2*>(&H[n].z));
        float2 f67 = __half22float2(*reinterpret_cast<__half2*>(&H[n].w));
        float nb[Cc] = {f01.x, f01.y, f23.x, f23.y,
                        f45.x, f45.y, f67.x, f67.y, X8[n]};
        u64 nbp[4] = {pk2(nb[0], nb[1]), pk2(nb[2], nb[3]),
                      pk2(nb[4], nb[5]), pk2(nb[6], nb[7])};

        float e[Cc], sum = 0.0f;
        #pragma unroll
        for (int c = 0; c < Cc; c++) {
            e[c] = __expf(xv[c] - nb[c]);
            sum += e[c];
        }
        float rr = ((vmask >> n) & 1u) ? __fdividef(1.0f, sum) : 0.0f;

        #pragma unroll
        for (int k = 0; k < Cc; k++) {
            float qk = e[k] * rr;
            u64 qq = pk2(qk, qk);
            s2[k][0] = ffma2(qq, nbp[0], s2[k][0]);
            s2[k][1] = ffma2(qq, nbp[1], s2[k][1]);
            s2[k][2] = ffma2(qq, nbp[2], s2[k][2]);
            s2[k][3] = ffma2(qq, nbp[3], s2[k][3]);
            s8c[k]   = fmaf(qk, nb[8], s8c[k]);
        }
    }

    // reduce across the lane pair; both lanes get FULL s
    #pragma unroll
    for (int k = 0; k < Cc; k++) {
        #pragma unroll
        for (int j = 0; j < 4; j++) {
            u64 o = __shfl_xor_sync(0xffffffffu, s2[k][j], 1);
            float x0f, x1f, y0f, y1f;
            upk2(s2[k][j], x0f, x1f);
            upk2(o,        y0f, y1f);
            s2[k][j] = pk2(x0f + y0f, x1f + y1f);
        }
        s8c[k] += __shfl_xor_sync(0xffffffffu, s8c[k], 1);
    }

    // lane p contracts full s into its o-half [8p, 8p+8)
    u64 ac[4] = {0ULL, 0ULL, 0ULL, 0ULL};
    const float* wb = Wsh + 8 * p;
    #pragma unroll
    for (int j = 0; j < 4; j++) {
        #pragma unroll
        for (int k = 0; k < Cc; k++) {
            float sc0, sc1;
            upk2(s2[k][j], sc0, sc1);
            {
                u64 ss = pk2(sc0, sc0);
                const ulonglong2* wr = reinterpret_cast<const ulonglong2*>(
                    wb + ((2 * j) * Cc + k) * OUTc);
                ulonglong2 wA = wr[0], wB = wr[1];
                ac[0] = ffma2(ss, wA.x, ac[0]);
                ac[1] = ffma2(ss, wA.y, ac[1]);
                ac[2] = ffma2(ss, wB.x, ac[2]);
                ac[3] = ffma2(ss, wB.y, ac[3]);
            }
            {
                u64 ss = pk2(sc1, sc1);
                const ulonglong2* wr = reinterpret_cast<const ulonglong2*>(
                    wb + ((2 * j + 1) * Cc + k) * OUTc);
                ulonglong2 wA = wr[0], wB = wr[1];
                ac[0] = ffma2(ss, wA.x, ac[0]);
                ac[1] = ffma2(ss, wA.y, ac[1]);
                ac[2] = ffma2(ss, wB.x, ac[2]);
                ac[3] = ffma2(ss, wB.y, ac[3]);
            }
        }
    }
    #pragma unroll
    for (int k = 0; k < Cc; k++) {          // c = 8
        u64 ss = pk2(s8c[k], s8c[k]);
        const ulonglong2* wr = reinterpret_cast<const ulonglong2*>(
            wb + (8 * Cc + k) * OUTc);
        ulonglong2 wA = wr[0], wB = wr[1];
        ac[0] = ffma2(ss, wA.x, ac[0]);
        ac[1] = ffma2(ss, wA.y, ac[1]);
        ac[2] = ffma2(ss, wB.x, ac[2]);
        ac[3] = ffma2(ss, wB.y, ac[3]);
    }

    // unpack, scale, relu, store two coalesced float4
    float r0f, r1f, r2f, r3f, r4f, r5f, r6f, r7f;
    upk2(ac[0], r0f, r1f);
    upk2(ac[1], r2f, r3f);
    upk2(ac[2], r4f, r5f);
    upk2(ac[3], r6f, r7f);

    float* op = out + (size_t)group * OUTc + 8 * p;
    float4 o0, o1;
    o0.x = fmaxf(r0f * invdeg, 0.0f);
    o0.y = fmaxf(r1f * invdeg, 0.0f);
    o0.z = fmaxf(r2f * invdeg, 0.0f);
    o0.w = fmaxf(r3f * invdeg, 0.0f);
    o1.x = fmaxf(r4f * invdeg, 0.0f);
    o1.y = fmaxf(r5f * invdeg, 0.0f);
    o1.z = fmaxf(r6f * invdeg, 0.0f);
    o1.w = fmaxf(r7f * invdeg, 0.0f);
    *reinterpret_cast<float4*>(op)     = o0;
    *reinterpret_cast<float4*>(op + 4) = o1;
}

extern "C" void kernel_launch(void* const* d_in, const int* in_sizes, int n_in,
                              void* d_out, int out_size)
{
    const float* x   = (const float*)d_in[0];   // (2, 20000, 9)
    const float* W   = (const float*)d_in[1];   // (9, 9, 16)
    const int*   adj = (const int*)d_in[2];     // (20000, 16)
    float*       out = (float*)d_out;           // (2, 20000, 16)

    {
        const int total   = Bc * Vc;            // 40000
        const int threads = 256;
        pad_kernel<<<(total + threads - 1) / threads, threads>>>(x);
    }
    {
        const int total   = Bc * Vc * 2;        // 80000 threads
        const int threads = 128;
        nlayer_kernel<<<total / threads, threads>>>(x, W, adj, out);
    }
}